// round 6
// baseline (speedup 1.0000x reference)
#include <cuda_runtime.h>

#define HID 50
#define NPTS 8192
#define NPARA 5000
#define WARPS_PER_BLOCK 8
#define THREADS (WARPS_PER_BLOCK * 32)
#define NBLOCKS (NPTS / WARPS_PER_BLOCK)

// shared layout (floats)
#define OFF_WIN 0
#define OFF_BIN 150
#define OFF_WH  200
#define OFF_BH  10200
#define OFF_WO  10400
#define OFF_BO  10500
#define OFF_STATE 10504                 // byte 42016, 16B aligned
// per warp: stA 50 units * 4 floats (16B stride) + stB 50 units * 2 floats (8B stride)
#define STATE_STRIDE 300                // 1200B per warp, keeps 16B alignment per warp
#define OFF_OUT8 (OFF_STATE + WARPS_PER_BLOCK * STATE_STRIDE)   // 12904
#define OFF_PART (OFF_OUT8 + WARPS_PER_BLOCK * 8)               // 12968
#define SMEM_FLOATS (OFF_PART + WARPS_PER_BLOCK * 6)            // 13016
#define SMEM_BYTES (SMEM_FLOATS * 4)    // ~52.1 KB -> 4 blocks/SM

__device__ double g_sums[6];            // zero-initialized at load; reset after finalize

// tanh(z) and sech^2(z): r = 1/(e^{2z}+1); h = 1-2r; 1-h^2 = 4r(1-r)
__device__ __forceinline__ void tanh_s(float z, float& h, float& s) {
    float e = __expf(2.0f * z);
    float r = __fdividef(1.0f, e + 1.0f);
    h = 1.0f - 2.0f * r;
    s = 4.0f * r * (1.0f - r);
}

__global__ void __launch_bounds__(THREADS) pinn_kernel(
    const float* __restrict__ x,
    const float* __restrict__ W_in, const float* __restrict__ b_in,
    const float* __restrict__ W_hid, const float* __restrict__ b_hid,
    const float* __restrict__ W_out, const float* __restrict__ b_out)
{
    extern __shared__ float sm[];
    const int tid = threadIdx.x;

    for (int i = tid; i < 2500; i += THREADS)
        ((float4*)(sm + OFF_WH))[i] = ((const float4*)W_hid)[i];
    for (int i = tid; i < 150;  i += THREADS) sm[OFF_WIN + i] = W_in[i];
    for (int i = tid; i < 50;   i += THREADS) sm[OFF_BIN + i] = b_in[i];
    for (int i = tid; i < 200;  i += THREADS) sm[OFF_BH  + i] = b_hid[i];
    for (int i = tid; i < 100;  i += THREADS) sm[OFF_WO  + i] = W_out[i];
    if (tid < 2) sm[OFF_BO + tid] = b_out[tid];
    __syncthreads();

    const int warp = tid >> 5;
    const int lane = tid & 31;
    const int point = blockIdx.x * WARPS_PER_BLOCK + warp;
    float* stA = sm + OFF_STATE + warp * STATE_STRIDE;   // 50 x {h,dx,dxx,dy}, 16B stride
    float* stB = stA + 200;                              // 50 x {dyy,dt},      8B stride

    const float x0 = x[point * 3 + 0];
    const float x1 = x[point * 3 + 1];
    const float x2 = x[point * 3 + 2];

    // ---- input layer: z = x @ W_in + b_in; first derivs = W_in rows; z'' = 0
    #pragma unroll
    for (int o = 0; o < 2; o++) {
        int j = lane + 32 * o;
        if (j < HID) {
            float w0 = sm[OFF_WIN + j];
            float w1 = sm[OFF_WIN + 50 + j];
            float w2 = sm[OFF_WIN + 100 + j];
            float z = sm[OFF_BIN + j] + x0 * w0 + x1 * w1 + x2 * w2;
            float h, s; tanh_s(z, h, s);
            float d0  = s * w0;
            float dd0 = -2.0f * h * d0 * w0;
            float d1  = s * w1;
            float dd1 = -2.0f * h * d1 * w1;
            float d2  = s * w2;
            ((float4*)stA)[j] = make_float4(h, d0, dd0, d1);   // STS.128 conflict-free
            ((float2*)stB)[j] = make_float2(dd1, d2);          // STS.64  conflict-free
        }
    }
    __syncwarp();

    // ---- 4 hidden layers: 6-channel matvec + tanh chain rule
    const int j1 = lane;
    const int j2 = lane + 32;
    const bool has2 = (j2 < HID);

    for (int l = 0; l < 4; l++) {
        const float* Wl = sm + OFF_WH + l * 2500;
        const float* bl = sm + OFF_BH + l * 50;

        float a00 = bl[j1],              a01 = has2 ? bl[j2] : 0.0f;
        float a10 = 0.f, a11 = 0.f;
        float a20 = 0.f, a21 = 0.f;
        float a30 = 0.f, a31 = 0.f;
        float a40 = 0.f, a41 = 0.f;
        float a50 = 0.f, a51 = 0.f;

        #pragma unroll
        for (int k = 0; k < HID; k++) {
            float4 h03 = ((const float4*)stA)[k];    // {h,dx,dxx,dy} broadcast, 1 wf
            float2 h45 = ((const float2*)stB)[k];    // {dyy,dt}      broadcast, 1 wf
            float w1 = Wl[k * 50 + j1];              // 1 wf
            float w2 = has2 ? Wl[k * 50 + j2] : 0.0f;// 1 wf
            a00 = fmaf(h03.x, w1, a00); a01 = fmaf(h03.x, w2, a01);
            a10 = fmaf(h03.y, w1, a10); a11 = fmaf(h03.y, w2, a11);
            a20 = fmaf(h03.z, w1, a20); a21 = fmaf(h03.z, w2, a21);
            a30 = fmaf(h03.w, w1, a30); a31 = fmaf(h03.w, w2, a31);
            a40 = fmaf(h45.x, w1, a40); a41 = fmaf(h45.x, w2, a41);
            a50 = fmaf(h45.y, w1, a50); a51 = fmaf(h45.y, w2, a51);
        }
        __syncwarp();   // all reads of old state complete before overwrite
        {
            float h, s; tanh_s(a00, h, s);
            float d0  = s * a10;
            float dd0 = fmaf(-2.0f * h * d0, a10, s * a20);
            float d1  = s * a30;
            float dd1 = fmaf(-2.0f * h * d1, a30, s * a40);
            float d2  = s * a50;
            ((float4*)stA)[j1] = make_float4(h, d0, dd0, d1);
            ((float2*)stB)[j1] = make_float2(dd1, d2);
        }
        if (has2) {
            float h, s; tanh_s(a01, h, s);
            float d0  = s * a11;
            float dd0 = fmaf(-2.0f * h * d0, a11, s * a21);
            float d1  = s * a31;
            float dd1 = fmaf(-2.0f * h * d1, a31, s * a41);
            float d2  = s * a51;
            ((float4*)stA)[j2] = make_float4(h, d0, dd0, d1);
            ((float2*)stB)[j2] = make_float2(dd1, d2);
        }
        __syncwarp();
    }

    // ---- output layer: channels {val,dxx,dyy,dt} x outputs {u,v} = 8 dot products
    if (lane < 8) {
        int cidx = lane >> 1;            // 0=val, 1=dxx, 2=dyy, 3=dt
        int o = lane & 1;
        const float* cp = (cidx < 2) ? (stA + 2 * cidx) : (stB + (cidx - 2));
        int cstr = (cidx < 2) ? 4 : 2;
        float acc0 = (cidx == 0) ? sm[OFF_BO + o] : 0.0f;
        float acc1 = 0.0f;
        #pragma unroll
        for (int k = 0; k < HID; k += 2) {
            acc0 = fmaf(cp[k * cstr],       sm[OFF_WO + k * 2 + o],       acc0);
            acc1 = fmaf(cp[(k + 1) * cstr], sm[OFF_WO + (k + 1) * 2 + o], acc1);
        }
        sm[OFF_OUT8 + warp * 8 + lane] = acc0 + acc1;
    }
    __syncwarp();

    if (lane == 0) {
        const float* o8 = sm + OFF_OUT8 + warp * 8;
        float u   = o8[0], v   = o8[1];
        float uxx = o8[2], vxx = o8[3];
        float uyy = o8[4], vyy = o8[5];
        float ut  = o8[6], vt  = o8[7];
        float Q  = u * u + v * v;
        float A1 = vt - 0.5f * uxx - 0.5f * vyy - Q * u + v;
        float A2 = ut + 0.5f * vxx - 0.5f * uyy + Q * v + u;
        float B1 = uyy, B2 = vyy;
        float C1 = Q * v, C2 = Q * u;
        float* pp = sm + OFF_PART + warp * 6;
        pp[0] = A1 * A1 + A2 * A2;
        pp[1] = B1 * B1 + B2 * B2;
        pp[2] = C1 * C1 + C2 * C2;
        pp[3] = A2 * B2 - A1 * B1;
        pp[4] = A1 * C1 + A2 * C2;
        pp[5] = B1 * C1 - B2 * C2;
    }
    __syncthreads();

    if (tid < 6) {
        double s = 0.0;
        #pragma unroll
        for (int w = 0; w < WARPS_PER_BLOCK; w++)
            s += (double)sm[OFF_PART + w * 6 + tid];
        atomicAdd(&g_sums[tid], s);
    }
}

__global__ void finalize_kernel(const float* __restrict__ para, float* __restrict__ out) {
    int p = blockIdx.x * blockDim.x + threadIdx.x;
    if (p < NPARA) {
        double a = (double)para[p * 3 + 0];
        double c = (double)para[p * 3 + 2];
        double r = g_sums[0]
                 + 0.25 * a * a * g_sums[1]
                 + c * c * g_sums[2]
                 + a * g_sums[3]
                 - 2.0 * c * g_sums[4]
                 + a * c * g_sums[5];
        out[p] = (float)(r * (1.0 / (double)NPTS));
    }
}

__global__ void reset_kernel() {
    if (threadIdx.x < 6) g_sums[threadIdx.x] = 0.0;
}

extern "C" void kernel_launch(void* const* d_in, const int* in_sizes, int n_in,
                              void* d_out, int out_size) {
    const float* x     = (const float*)d_in[0];
    const float* para  = (const float*)d_in[1];
    const float* W_in  = (const float*)d_in[2];
    const float* b_in  = (const float*)d_in[3];
    const float* W_hid = (const float*)d_in[4];
    const float* b_hid = (const float*)d_in[5];
    const float* W_out = (const float*)d_in[6];
    const float* b_out = (const float*)d_in[7];
    float* out = (float*)d_out;

    cudaFuncSetAttribute(pinn_kernel, cudaFuncAttributeMaxDynamicSharedMemorySize, SMEM_BYTES);
    pinn_kernel<<<NBLOCKS, THREADS, SMEM_BYTES>>>(
        x, W_in, b_in, W_hid, b_hid, W_out, b_out);
    finalize_kernel<<<(NPARA + 255) / 256, 256>>>(para, out);
    reset_kernel<<<1, 32>>>();   // reset AFTER finalize (replay-safe, launch-ordered)
}

// round 7
// speedup vs baseline: 1.0856x; 1.0856x over previous
#include <cuda_runtime.h>

#define HID 50
#define NPTS 8192
#define NPARA 5000
#define WARPS_PER_BLOCK 8
#define THREADS (WARPS_PER_BLOCK * 32)
#define PTS_PER_BLOCK (WARPS_PER_BLOCK * 2)
#define NBLOCKS (NPTS / PTS_PER_BLOCK)   // 512

// shared layout (floats)
#define OFF_WIN 0
#define OFF_BIN 150
#define OFF_WH  200
#define OFF_BH  10200
#define OFF_WO  10400
#define OFF_BO  10500
#define OFF_STATE 10504                 // 16B aligned
// per warp: 2 points x (stA 50x4 + stB 50x2) = 600 floats
#define STATE_STRIDE 600
#define OFF_OUT16 (OFF_STATE + WARPS_PER_BLOCK * STATE_STRIDE)  // 15304
#define OFF_PART (OFF_OUT16 + WARPS_PER_BLOCK * 16)             // 15432
#define SMEM_FLOATS (OFF_PART + WARPS_PER_BLOCK * 12)           // 15528
#define SMEM_BYTES (SMEM_FLOATS * 4)    // ~60.7 KB -> 3 blocks/SM

__device__ double g_sums[6];            // zero-initialized at load; reset after finalize

// tanh(z) and sech^2(z): r = 1/(e^{2z}+1); h = 1-2r; 1-h^2 = 4r(1-r)
__device__ __forceinline__ void tanh_s(float z, float& h, float& s) {
    float e = __expf(2.0f * z);
    float r = __fdividef(1.0f, e + 1.0f);
    h = 1.0f - 2.0f * r;
    s = 4.0f * r * (1.0f - r);
}

// tanh chain + split-array state write for one unit of one point
__device__ __forceinline__ void chain_store(float* stA, float* stB, int j,
                                            float z, float zx, float zxx,
                                            float zy, float zyy, float zt) {
    float h, s; tanh_s(z, h, s);
    float d0  = s * zx;
    float dd0 = fmaf(-2.0f * h * d0, zx, s * zxx);
    float d1  = s * zy;
    float dd1 = fmaf(-2.0f * h * d1, zy, s * zyy);
    float d2  = s * zt;
    ((float4*)stA)[j] = make_float4(h, d0, dd0, d1);
    ((float2*)stB)[j] = make_float2(dd1, d2);
}

__global__ void __launch_bounds__(THREADS) pinn_kernel(
    const float* __restrict__ x,
    const float* __restrict__ W_in, const float* __restrict__ b_in,
    const float* __restrict__ W_hid, const float* __restrict__ b_hid,
    const float* __restrict__ W_out, const float* __restrict__ b_out)
{
    extern __shared__ float sm[];
    const int tid = threadIdx.x;

    for (int i = tid; i < 2500; i += THREADS)
        ((float4*)(sm + OFF_WH))[i] = ((const float4*)W_hid)[i];
    for (int i = tid; i < 150;  i += THREADS) sm[OFF_WIN + i] = W_in[i];
    for (int i = tid; i < 50;   i += THREADS) sm[OFF_BIN + i] = b_in[i];
    for (int i = tid; i < 200;  i += THREADS) sm[OFF_BH  + i] = b_hid[i];
    for (int i = tid; i < 100;  i += THREADS) sm[OFF_WO  + i] = W_out[i];
    if (tid < 2) sm[OFF_BO + tid] = b_out[tid];
    __syncthreads();

    const int warp = tid >> 5;
    const int lane = tid & 31;
    const int p0 = blockIdx.x * PTS_PER_BLOCK + warp * 2;   // this warp: points p0, p0+1
    float* stA0 = sm + OFF_STATE + warp * STATE_STRIDE;     // point0: 50x{h,dx,dxx,dy}
    float* stB0 = stA0 + 200;                               //         50x{dyy,dt}
    float* stA1 = stA0 + 300;                               // point1
    float* stB1 = stA1 + 200;

    const float x00 = x[p0 * 3 + 0], x01 = x[p0 * 3 + 1], x02 = x[p0 * 3 + 2];
    const float x10 = x[p0 * 3 + 3], x11 = x[p0 * 3 + 4], x12 = x[p0 * 3 + 5];

    // ---- input layer for both points
    #pragma unroll
    for (int o = 0; o < 2; o++) {
        int j = lane + 32 * o;
        if (j < HID) {
            float w0 = sm[OFF_WIN + j];
            float w1 = sm[OFF_WIN + 50 + j];
            float w2 = sm[OFF_WIN + 100 + j];
            float bj = sm[OFF_BIN + j];
            {
                float z = bj + x00 * w0 + x01 * w1 + x02 * w2;
                float h, s; tanh_s(z, h, s);
                float d0 = s * w0, dd0 = -2.0f * h * d0 * w0;
                float d1 = s * w1, dd1 = -2.0f * h * d1 * w1;
                float d2 = s * w2;
                ((float4*)stA0)[j] = make_float4(h, d0, dd0, d1);
                ((float2*)stB0)[j] = make_float2(dd1, d2);
            }
            {
                float z = bj + x10 * w0 + x11 * w1 + x12 * w2;
                float h, s; tanh_s(z, h, s);
                float d0 = s * w0, dd0 = -2.0f * h * d0 * w0;
                float d1 = s * w1, dd1 = -2.0f * h * d1 * w1;
                float d2 = s * w2;
                ((float4*)stA1)[j] = make_float4(h, d0, dd0, d1);
                ((float2*)stB1)[j] = make_float2(dd1, d2);
            }
        }
    }
    __syncwarp();

    // ---- 4 hidden layers: shared weight loads, 2 points, 24 FMA per k
    const int j1 = lane;
    const int j2 = lane + 32;
    const bool has2 = (j2 < HID);

    for (int l = 0; l < 4; l++) {
        const float* Wl = sm + OFF_WH + l * 2500;
        const float* bl = sm + OFF_BH + l * 50;
        float b1 = bl[j1], b2 = has2 ? bl[j2] : 0.0f;

        // point0 accumulators
        float p000 = b1, p001 = b2;
        float p010 = 0.f, p011 = 0.f, p020 = 0.f, p021 = 0.f;
        float p030 = 0.f, p031 = 0.f, p040 = 0.f, p041 = 0.f;
        float p050 = 0.f, p051 = 0.f;
        // point1 accumulators
        float p100 = b1, p101 = b2;
        float p110 = 0.f, p111 = 0.f, p120 = 0.f, p121 = 0.f;
        float p130 = 0.f, p131 = 0.f, p140 = 0.f, p141 = 0.f;
        float p150 = 0.f, p151 = 0.f;

        #pragma unroll
        for (int k = 0; k < HID; k++) {
            float w1 = Wl[k * 50 + j1];
            float w2 = has2 ? Wl[k * 50 + j2] : 0.0f;
            float4 A0 = ((const float4*)stA0)[k];
            float2 B0 = ((const float2*)stB0)[k];
            float4 A1 = ((const float4*)stA1)[k];
            float2 B1 = ((const float2*)stB1)[k];
            p000 = fmaf(A0.x, w1, p000); p001 = fmaf(A0.x, w2, p001);
            p010 = fmaf(A0.y, w1, p010); p011 = fmaf(A0.y, w2, p011);
            p020 = fmaf(A0.z, w1, p020); p021 = fmaf(A0.z, w2, p021);
            p030 = fmaf(A0.w, w1, p030); p031 = fmaf(A0.w, w2, p031);
            p040 = fmaf(B0.x, w1, p040); p041 = fmaf(B0.x, w2, p041);
            p050 = fmaf(B0.y, w1, p050); p051 = fmaf(B0.y, w2, p051);
            p100 = fmaf(A1.x, w1, p100); p101 = fmaf(A1.x, w2, p101);
            p110 = fmaf(A1.y, w1, p110); p111 = fmaf(A1.y, w2, p111);
            p120 = fmaf(A1.z, w1, p120); p121 = fmaf(A1.z, w2, p121);
            p130 = fmaf(A1.w, w1, p130); p131 = fmaf(A1.w, w2, p131);
            p140 = fmaf(B1.x, w1, p140); p141 = fmaf(B1.x, w2, p141);
            p150 = fmaf(B1.y, w1, p150); p151 = fmaf(B1.y, w2, p151);
        }
        __syncwarp();   // all reads of old state complete before overwrite
        chain_store(stA0, stB0, j1, p000, p010, p020, p030, p040, p050);
        chain_store(stA1, stB1, j1, p100, p110, p120, p130, p140, p150);
        if (has2) {
            chain_store(stA0, stB0, j2, p001, p011, p021, p031, p041, p051);
            chain_store(stA1, stB1, j2, p101, p111, p121, p131, p141, p151);
        }
        __syncwarp();
    }

    // ---- output layer: 8 dot products per point; lanes 0-7 pt0, 8-15 pt1
    if (lane < 16) {
        int pt = lane >> 3;
        int l8 = lane & 7;
        int cidx = l8 >> 1;              // 0=val, 1=dxx, 2=dyy, 3=dt
        int o = l8 & 1;
        float* sA = pt ? stA1 : stA0;
        float* sB = pt ? stB1 : stB0;
        const float* cp = (cidx < 2) ? (sA + 2 * cidx) : (sB + (cidx - 2));
        int cstr = (cidx < 2) ? 4 : 2;
        float acc0 = (cidx == 0) ? sm[OFF_BO + o] : 0.0f;
        float acc1 = 0.0f;
        #pragma unroll
        for (int k = 0; k < HID; k += 2) {
            acc0 = fmaf(cp[k * cstr],       sm[OFF_WO + k * 2 + o],       acc0);
            acc1 = fmaf(cp[(k + 1) * cstr], sm[OFF_WO + (k + 1) * 2 + o], acc1);
        }
        sm[OFF_OUT16 + warp * 16 + lane] = acc0 + acc1;
    }
    __syncwarp();

    if (lane < 2) {                      // lane 0 -> pt0, lane 1 -> pt1
        const float* o8 = sm + OFF_OUT16 + warp * 16 + lane * 8;
        float u   = o8[0], v   = o8[1];
        float uxx = o8[2], vxx = o8[3];
        float uyy = o8[4], vyy = o8[5];
        float ut  = o8[6], vt  = o8[7];
        float Q  = u * u + v * v;
        float A1 = vt - 0.5f * uxx - 0.5f * vyy - Q * u + v;
        float A2 = ut + 0.5f * vxx - 0.5f * uyy + Q * v + u;
        float B1 = uyy, B2 = vyy;
        float C1 = Q * v, C2 = Q * u;
        float* pp = sm + OFF_PART + (warp * 2 + lane) * 6;
        pp[0] = A1 * A1 + A2 * A2;
        pp[1] = B1 * B1 + B2 * B2;
        pp[2] = C1 * C1 + C2 * C2;
        pp[3] = A2 * B2 - A1 * B1;
        pp[4] = A1 * C1 + A2 * C2;
        pp[5] = B1 * C1 - B2 * C2;
    }
    __syncthreads();

    if (tid < 6) {
        double s = 0.0;
        #pragma unroll
        for (int w = 0; w < WARPS_PER_BLOCK * 2; w++)
            s += (double)sm[OFF_PART + w * 6 + tid];
        atomicAdd(&g_sums[tid], s);
    }
}

__global__ void finalize_kernel(const float* __restrict__ para, float* __restrict__ out) {
    int p = blockIdx.x * blockDim.x + threadIdx.x;
    if (p < NPARA) {
        double a = (double)para[p * 3 + 0];
        double c = (double)para[p * 3 + 2];
        double r = g_sums[0]
                 + 0.25 * a * a * g_sums[1]
                 + c * c * g_sums[2]
                 + a * g_sums[3]
                 - 2.0 * c * g_sums[4]
                 + a * c * g_sums[5];
        out[p] = (float)(r * (1.0 / (double)NPTS));
    }
}

__global__ void reset_kernel() {
    if (threadIdx.x < 6) g_sums[threadIdx.x] = 0.0;
}

extern "C" void kernel_launch(void* const* d_in, const int* in_sizes, int n_in,
                              void* d_out, int out_size) {
    const float* x     = (const float*)d_in[0];
    const float* para  = (const float*)d_in[1];
    const float* W_in  = (const float*)d_in[2];
    const float* b_in  = (const float*)d_in[3];
    const float* W_hid = (const float*)d_in[4];
    const float* b_hid = (const float*)d_in[5];
    const float* W_out = (const float*)d_in[6];
    const float* b_out = (const float*)d_in[7];
    float* out = (float*)d_out;

    cudaFuncSetAttribute(pinn_kernel, cudaFuncAttributeMaxDynamicSharedMemorySize, SMEM_BYTES);
    pinn_kernel<<<NBLOCKS, THREADS, SMEM_BYTES>>>(
        x, W_in, b_in, W_hid, b_hid, W_out, b_out);
    finalize_kernel<<<(NPARA + 255) / 256, 256>>>(para, out);
    reset_kernel<<<1, 32>>>();   // reset AFTER finalize (replay-safe, launch-ordered)
}

// round 8
// speedup vs baseline: 1.1318x; 1.0425x over previous
#include <cuda_runtime.h>

#define HID 50
#define NPTS 8192
#define NPARA 5000
#define WARPS_PER_BLOCK 8
#define THREADS (WARPS_PER_BLOCK * 32)
#define NBLOCKS 296                      // exactly 2 CTAs per SM on 148 SMs
#define TOTAL_WARPS (NBLOCKS * WARPS_PER_BLOCK)   // 2368
#define NTASKS (NPTS / 2)                // 4096 two-point tasks

// shared layout (floats)
#define OFF_WIN 0
#define OFF_BIN 150
#define OFF_WH  200
#define OFF_BH  10200
#define OFF_WO  10400
#define OFF_BO  10500
#define OFF_STATE 10504                 // 16B aligned
// per warp: 2 points x (stA 50x4 + stB 50x2) = 600 floats
#define STATE_STRIDE 600
#define OFF_OUT16 (OFF_STATE + WARPS_PER_BLOCK * STATE_STRIDE)  // 15304
#define OFF_PART (OFF_OUT16 + WARPS_PER_BLOCK * 16)             // 15432
#define SMEM_FLOATS (OFF_PART + WARPS_PER_BLOCK * 12)           // 15528
#define SMEM_BYTES (SMEM_FLOATS * 4)    // ~60.7 KB -> 2 CTAs/SM easily

__device__ double g_sums[6];            // zero-initialized at load; reset after finalize

// tanh(z) and sech^2(z): r = 1/(e^{2z}+1); h = 1-2r; 1-h^2 = 4r(1-r)
__device__ __forceinline__ void tanh_s(float z, float& h, float& s) {
    float e = __expf(2.0f * z);
    float r = __fdividef(1.0f, e + 1.0f);
    h = 1.0f - 2.0f * r;
    s = 4.0f * r * (1.0f - r);
}

// tanh chain + split-array state write for one unit of one point
__device__ __forceinline__ void chain_store(float* stA, float* stB, int j,
                                            float z, float zx, float zxx,
                                            float zy, float zyy, float zt) {
    float h, s; tanh_s(z, h, s);
    float d0  = s * zx;
    float dd0 = fmaf(-2.0f * h * d0, zx, s * zxx);
    float d1  = s * zy;
    float dd1 = fmaf(-2.0f * h * d1, zy, s * zyy);
    float d2  = s * zt;
    ((float4*)stA)[j] = make_float4(h, d0, dd0, d1);
    ((float2*)stB)[j] = make_float2(dd1, d2);
}

__global__ void __launch_bounds__(THREADS) pinn_kernel(
    const float* __restrict__ x,
    const float* __restrict__ W_in, const float* __restrict__ b_in,
    const float* __restrict__ W_hid, const float* __restrict__ b_hid,
    const float* __restrict__ W_out, const float* __restrict__ b_out)
{
    extern __shared__ float sm[];
    const int tid = threadIdx.x;

    for (int i = tid; i < 2500; i += THREADS)
        ((float4*)(sm + OFF_WH))[i] = ((const float4*)W_hid)[i];
    for (int i = tid; i < 150;  i += THREADS) sm[OFF_WIN + i] = W_in[i];
    for (int i = tid; i < 50;   i += THREADS) sm[OFF_BIN + i] = b_in[i];
    for (int i = tid; i < 200;  i += THREADS) sm[OFF_BH  + i] = b_hid[i];
    for (int i = tid; i < 100;  i += THREADS) sm[OFF_WO  + i] = W_out[i];
    if (tid < 2) sm[OFF_BO + tid] = b_out[tid];
    for (int i = tid; i < WARPS_PER_BLOCK * 12; i += THREADS)
        sm[OFF_PART + i] = 0.0f;        // per-warp residual accumulators
    __syncthreads();

    const int warp = tid >> 5;
    const int lane = tid & 31;
    const int gwarp = blockIdx.x * WARPS_PER_BLOCK + warp;
    float* stA0 = sm + OFF_STATE + warp * STATE_STRIDE;     // point0: 50x{h,dx,dxx,dy}
    float* stB0 = stA0 + 200;                               //         50x{dyy,dt}
    float* stA1 = stA0 + 300;                               // point1
    float* stB1 = stA1 + 200;

    const int j1 = lane;
    const int j2 = lane + 32;
    const bool has2 = (j2 < HID);

    for (int task = gwarp; task < NTASKS; task += TOTAL_WARPS) {
        const int p0 = task * 2;
        const float x00 = x[p0 * 3 + 0], x01 = x[p0 * 3 + 1], x02 = x[p0 * 3 + 2];
        const float x10 = x[p0 * 3 + 3], x11 = x[p0 * 3 + 4], x12 = x[p0 * 3 + 5];
        __syncwarp();   // prior task's epilogue reads of st done before overwrite

        // ---- input layer for both points
        #pragma unroll
        for (int o = 0; o < 2; o++) {
            int j = lane + 32 * o;
            if (j < HID) {
                float w0 = sm[OFF_WIN + j];
                float w1 = sm[OFF_WIN + 50 + j];
                float w2 = sm[OFF_WIN + 100 + j];
                float bj = sm[OFF_BIN + j];
                {
                    float z = bj + x00 * w0 + x01 * w1 + x02 * w2;
                    float h, s; tanh_s(z, h, s);
                    float d0 = s * w0, dd0 = -2.0f * h * d0 * w0;
                    float d1 = s * w1, dd1 = -2.0f * h * d1 * w1;
                    float d2 = s * w2;
                    ((float4*)stA0)[j] = make_float4(h, d0, dd0, d1);
                    ((float2*)stB0)[j] = make_float2(dd1, d2);
                }
                {
                    float z = bj + x10 * w0 + x11 * w1 + x12 * w2;
                    float h, s; tanh_s(z, h, s);
                    float d0 = s * w0, dd0 = -2.0f * h * d0 * w0;
                    float d1 = s * w1, dd1 = -2.0f * h * d1 * w1;
                    float d2 = s * w2;
                    ((float4*)stA1)[j] = make_float4(h, d0, dd0, d1);
                    ((float2*)stB1)[j] = make_float2(dd1, d2);
                }
            }
        }
        __syncwarp();

        // ---- 4 hidden layers: shared weight loads, 2 points, 24 FMA per k
        for (int l = 0; l < 4; l++) {
            const float* Wl = sm + OFF_WH + l * 2500;
            const float* bl = sm + OFF_BH + l * 50;
            float b1 = bl[j1], b2 = has2 ? bl[j2] : 0.0f;

            float p000 = b1, p001 = b2;
            float p010 = 0.f, p011 = 0.f, p020 = 0.f, p021 = 0.f;
            float p030 = 0.f, p031 = 0.f, p040 = 0.f, p041 = 0.f;
            float p050 = 0.f, p051 = 0.f;
            float p100 = b1, p101 = b2;
            float p110 = 0.f, p111 = 0.f, p120 = 0.f, p121 = 0.f;
            float p130 = 0.f, p131 = 0.f, p140 = 0.f, p141 = 0.f;
            float p150 = 0.f, p151 = 0.f;

            #pragma unroll
            for (int k = 0; k < HID; k++) {
                float w1 = Wl[k * 50 + j1];
                float w2 = has2 ? Wl[k * 50 + j2] : 0.0f;
                float4 A0 = ((const float4*)stA0)[k];
                float2 B0 = ((const float2*)stB0)[k];
                float4 A1 = ((const float4*)stA1)[k];
                float2 B1 = ((const float2*)stB1)[k];
                p000 = fmaf(A0.x, w1, p000); p001 = fmaf(A0.x, w2, p001);
                p010 = fmaf(A0.y, w1, p010); p011 = fmaf(A0.y, w2, p011);
                p020 = fmaf(A0.z, w1, p020); p021 = fmaf(A0.z, w2, p021);
                p030 = fmaf(A0.w, w1, p030); p031 = fmaf(A0.w, w2, p031);
                p040 = fmaf(B0.x, w1, p040); p041 = fmaf(B0.x, w2, p041);
                p050 = fmaf(B0.y, w1, p050); p051 = fmaf(B0.y, w2, p051);
                p100 = fmaf(A1.x, w1, p100); p101 = fmaf(A1.x, w2, p101);
                p110 = fmaf(A1.y, w1, p110); p111 = fmaf(A1.y, w2, p111);
                p120 = fmaf(A1.z, w1, p120); p121 = fmaf(A1.z, w2, p121);
                p130 = fmaf(A1.w, w1, p130); p131 = fmaf(A1.w, w2, p131);
                p140 = fmaf(B1.x, w1, p140); p141 = fmaf(B1.x, w2, p141);
                p150 = fmaf(B1.y, w1, p150); p151 = fmaf(B1.y, w2, p151);
            }
            __syncwarp();   // all reads of old state complete before overwrite
            chain_store(stA0, stB0, j1, p000, p010, p020, p030, p040, p050);
            chain_store(stA1, stB1, j1, p100, p110, p120, p130, p140, p150);
            if (has2) {
                chain_store(stA0, stB0, j2, p001, p011, p021, p031, p041, p051);
                chain_store(stA1, stB1, j2, p101, p111, p121, p131, p141, p151);
            }
            __syncwarp();
        }

        // ---- output layer: 8 dot products per point; lanes 0-7 pt0, 8-15 pt1
        if (lane < 16) {
            int pt = lane >> 3;
            int l8 = lane & 7;
            int cidx = l8 >> 1;              // 0=val, 1=dxx, 2=dyy, 3=dt
            int o = l8 & 1;
            float* sA = pt ? stA1 : stA0;
            float* sB = pt ? stB1 : stB0;
            const float* cp = (cidx < 2) ? (sA + 2 * cidx) : (sB + (cidx - 2));
            int cstr = (cidx < 2) ? 4 : 2;
            float acc0 = (cidx == 0) ? sm[OFF_BO + o] : 0.0f;
            float acc1 = 0.0f;
            #pragma unroll
            for (int k = 0; k < HID; k += 2) {
                acc0 = fmaf(cp[k * cstr],       sm[OFF_WO + k * 2 + o],       acc0);
                acc1 = fmaf(cp[(k + 1) * cstr], sm[OFF_WO + (k + 1) * 2 + o], acc1);
            }
            sm[OFF_OUT16 + warp * 16 + lane] = acc0 + acc1;
        }
        __syncwarp();

        if (lane < 2) {                      // lane 0 -> pt0, lane 1 -> pt1
            const float* o8 = sm + OFF_OUT16 + warp * 16 + lane * 8;
            float u   = o8[0], v   = o8[1];
            float uxx = o8[2], vxx = o8[3];
            float uyy = o8[4], vyy = o8[5];
            float ut  = o8[6], vt  = o8[7];
            float Q  = u * u + v * v;
            float A1 = vt - 0.5f * uxx - 0.5f * vyy - Q * u + v;
            float A2 = ut + 0.5f * vxx - 0.5f * uyy + Q * v + u;
            float B1 = uyy, B2 = vyy;
            float C1 = Q * v, C2 = Q * u;
            float* pp = sm + OFF_PART + (warp * 2 + lane) * 6;
            pp[0] += A1 * A1 + A2 * A2;
            pp[1] += B1 * B1 + B2 * B2;
            pp[2] += C1 * C1 + C2 * C2;
            pp[3] += A2 * B2 - A1 * B1;
            pp[4] += A1 * C1 + A2 * C2;
            pp[5] += B1 * C1 - B2 * C2;
        }
    }
    __syncthreads();

    if (tid < 6) {
        double s = 0.0;
        #pragma unroll
        for (int w = 0; w < WARPS_PER_BLOCK * 2; w++)
            s += (double)sm[OFF_PART + w * 6 + tid];
        atomicAdd(&g_sums[tid], s);
    }
}

__global__ void finalize_kernel(const float* __restrict__ para, float* __restrict__ out) {
    int p = blockIdx.x * blockDim.x + threadIdx.x;
    if (p < NPARA) {
        double a = (double)para[p * 3 + 0];
        double c = (double)para[p * 3 + 2];
        double r = g_sums[0]
                 + 0.25 * a * a * g_sums[1]
                 + c * c * g_sums[2]
                 + a * g_sums[3]
                 - 2.0 * c * g_sums[4]
                 + a * c * g_sums[5];
        out[p] = (float)(r * (1.0 / (double)NPTS));
    }
}

__global__ void reset_kernel() {
    if (threadIdx.x < 6) g_sums[threadIdx.x] = 0.0;
}

extern "C" void kernel_launch(void* const* d_in, const int* in_sizes, int n_in,
                              void* d_out, int out_size) {
    const float* x     = (const float*)d_in[0];
    const float* para  = (const float*)d_in[1];
    const float* W_in  = (const float*)d_in[2];
    const float* b_in  = (const float*)d_in[3];
    const float* W_hid = (const float*)d_in[4];
    const float* b_hid = (const float*)d_in[5];
    const float* W_out = (const float*)d_in[6];
    const float* b_out = (const float*)d_in[7];
    float* out = (float*)d_out;

    cudaFuncSetAttribute(pinn_kernel, cudaFuncAttributeMaxDynamicSharedMemorySize, SMEM_BYTES);
    pinn_kernel<<<NBLOCKS, THREADS, SMEM_BYTES>>>(
        x, W_in, b_in, W_hid, b_hid, W_out, b_out);
    finalize_kernel<<<(NPARA + 255) / 256, 256>>>(para, out);
    reset_kernel<<<1, 32>>>();   // reset AFTER finalize (replay-safe, launch-ordered)
}